// round 1
// baseline (speedup 1.0000x reference)
#include <cuda_runtime.h>
#include <math.h>

// Problem constants
#define Bsz   512
#define NA    8
#define OB    160
#define SD    256
#define NH    4      // heads H
#define GD    64
#define KD    65
#define NU    32
#define Ntot  4096   // B*NA
#define KDSQ  4225   // KD*KD

// Output layout (flat concat of reference tuple, fp32):
//   [0, 512)            q_tot + v            [B,1,1]
//   [512, 16896)        attn                 [B,H,1,NA]
//   [16896, 67125760)   gnn_weight_matrics   [N,N,H]
#define OUT_ATTN  512
#define OUT_DENSE 16896
#define DENSE_F4  16777216ULL   // 67108864 floats / 4

// Scratch (device globals; no allocation allowed)
__device__ float g_keys_pre[Ntot * KD];        // [n][KD]  concat(agent_q, gcn)
__device__ float g_alpha[Bsz * NA * NA * NH];  // [b][i][j][h]
__device__ float g_part[5 * Ntot * KD];        // k-group partials of hypernet reduce

// ---------------------------------------------------------------------------
// Kernel A: per-batch GAT (graph is the deterministic fully-connected 8-node
// graph, so edge_index is ignored). Produces alpha (for dense output + agg)
// and keys_pre = concat(agent_qs, relu(mean-head aggregation)).
// ---------------------------------------------------------------------------
__global__ __launch_bounds__(256) void kA(const float* __restrict__ aq,
                                          const float* __restrict__ obs,
                                          const float* __restrict__ Wg,
                                          const float* __restrict__ bg,
                                          const float* __restrict__ asrc,
                                          const float* __restrict__ adst) {
    int b = blockIdx.x, t = threadIdx.x;
    __shared__ float obs_s[NA][OB + 1];
    __shared__ float h_s[NA][GD];
    __shared__ float ss[NA][NH], ds[NA][NH];
    __shared__ float al[NA][NA][NH];   // [src i][dst j][head]

    const float* ob = obs + (size_t)b * NA * OB;
    for (int i = t; i < NA * OB; i += 256) obs_s[i / OB][i % OB] = ob[i];
    __syncthreads();

    // h = obs @ W_gnn + b_gnn   (8x64 outputs)
    for (int idx = t; idx < NA * GD; idx += 256) {
        int a = idx >> 6, g = idx & 63;
        float acc = bg[g];
        #pragma unroll 8
        for (int o = 0; o < OB; o++) acc += obs_s[a][o] * Wg[o * GD + g];
        h_s[a][g] = acc;
    }
    __syncthreads();

    // per-node per-head src/dst scores
    if (t < 64) {
        int a = t >> 3, hh = (t >> 1) & 3, sd = t & 1;
        const float* av = (sd ? adst : asrc) + hh * GD;
        float acc = 0.f;
        #pragma unroll
        for (int g = 0; g < GD; g++) acc += h_s[a][g] * av[g];
        if (sd) ds[a][hh] = acc; else ss[a][hh] = acc;
    }
    __syncthreads();

    // per-(dst j, head): leaky_relu + segment softmax over the 7 sources
    if (t < 32) {
        int j = t >> 2, hh = t & 3;
        float e[NA]; float m = -1e30f;
        #pragma unroll
        for (int i = 0; i < NA; i++) {
            if (i == j) { e[i] = -1e30f; continue; }
            float x = ss[i][hh] + ds[j][hh];
            x = x > 0.f ? x : 0.2f * x;
            e[i] = x; m = fmaxf(m, x);
        }
        float s = 0.f;
        #pragma unroll
        for (int i = 0; i < NA; i++) {
            float ex = (i == j) ? 0.f : expf(e[i] - m);
            e[i] = ex; s += ex;
        }
        float inv = 1.f / (s + 1e-16f);
        #pragma unroll
        for (int i = 0; i < NA; i++) al[i][j][hh] = e[i] * inv;
    }
    __syncthreads();

    // dump alpha for the dense-output scatter (kernel C)
    for (int idx = t; idx < NA * NA * NH; idx += 256)
        g_alpha[b * 256 + idx] = ((const float*)al)[idx];

    // agg[j,g] = 0.25 * sum_{i,h} alpha[i,j,h]*h[i,g];  gcn = relu
    for (int idx = t; idx < NA * GD; idx += 256) {
        int j = idx >> 6, g = idx & 63;
        float acc = 0.f;
        #pragma unroll
        for (int i = 0; i < NA; i++) {
            float aw = al[i][j][0] + al[i][j][1] + al[i][j][2] + al[i][j][3];
            acc += h_s[i][g] * aw;
        }
        float gcn = fmaxf(0.25f * acc, 0.f);
        g_keys_pre[(size_t)(b * NA + j) * KD + 1 + g] = gcn;
        if (g == 0) g_keys_pre[(size_t)(b * NA + j) * KD] = aq[b * NA + j];
    }
}

// ---------------------------------------------------------------------------
// Kernel B: fused hypernet GEMM + weighted-abs reduce + interleaved zero-fill
// of the 268MB dense output region.
//   partial[n,j] (per k-group) = sum_{k in group} keys_pre[n,k] *
//                                |obs[n,:]·W_h[:,k*65+j] + b_h[k*65+j]|
// Grid: 128 n-tiles (32 rows) x 5 k-groups (13 k each) = 640 blocks.
// 260 active compute threads: 4 rowgroups(8 rows) x 65 cols.
// ---------------------------------------------------------------------------
#define TBB 288
#define TM  32
#define KGS 13
__global__ __launch_bounds__(TBB) void kB(const float* __restrict__ obs,
                                          const float* __restrict__ Wh,
                                          const float* __restrict__ bh,
                                          float* __restrict__ dout) {
    __shared__ float obs_s[OB][36];        // o-major, padded for LDS.128
    __shared__ float W_s[80 * KD];         // half of one k-slab [80][65]
    __shared__ float keys_s[TM][KGS];

    int nt = blockIdx.x & 127;             // n tile
    int kg = blockIdx.x >> 7;              // 0..4
    int n0 = nt * TM;
    int t = threadIdx.x;

    // interleaved zero-fill state (grid-strided over whole dense region)
    float4* zp = (float4*)(dout + OUT_DENSE);
    unsigned long long zi = (unsigned long long)blockIdx.x * TBB + t;
    const unsigned long long zstride = 640ULL * TBB;

    // stage obs tile o-major
    for (int idx = t; idx < TM * OB; idx += TBB) {
        int r = idx / OB, o = idx % OB;
        obs_s[o][r] = obs[(size_t)(n0 + r) * OB + o];
    }
    for (int idx = t; idx < TM * KGS; idx += TBB) {
        int r = idx / KGS, kk = idx % KGS;
        keys_s[r][kk] = g_keys_pre[(size_t)(n0 + r) * KD + kg * KGS + kk];
    }
    __syncthreads();

    int rg = t / KD, j = t % KD;           // rowgroup, output column
    bool act = (t < 4 * KD);

    float acc[8];
    #pragma unroll
    for (int i = 0; i < 8; i++) acc[i] = 0.f;

    for (int kk = 0; kk < KGS; kk++) {
        int k = kg * KGS + kk;
        float c[8];
        #pragma unroll
        for (int i = 0; i < 8; i++) c[i] = 0.f;

        for (int half = 0; half < 2; half++) {
            __syncthreads();
            int o0 = half * 80;
            for (int idx = t; idx < 80 * KD; idx += TBB) {
                int o = idx / KD, jj = idx % KD;
                W_s[idx] = Wh[(size_t)(o0 + o) * KDSQ + k * KD + jj];
            }
            __syncthreads();

            // fire-and-forget zero stores (hide DRAM writes under FMA)
            #pragma unroll
            for (int z = 0; z < 4; z++) {
                if (zi < DENSE_F4) zp[zi] = make_float4(0.f, 0.f, 0.f, 0.f);
                zi += zstride;
            }

            if (act) {
                #pragma unroll 4
                for (int o = 0; o < 80; o++) {
                    const float4* op = (const float4*)&obs_s[o0 + o][rg * 8];
                    float4 A0 = op[0], A1 = op[1];
                    float w = W_s[o * KD + j];
                    c[0] += A0.x * w; c[1] += A0.y * w;
                    c[2] += A0.z * w; c[3] += A0.w * w;
                    c[4] += A1.x * w; c[5] += A1.y * w;
                    c[6] += A1.z * w; c[7] += A1.w * w;
                }
            }
        }
        if (act) {
            float bias = bh[k * KD + j];
            #pragma unroll
            for (int i = 0; i < 8; i++)
                acc[i] += keys_s[rg * 8 + i][kk] * fabsf(c[i] + bias);
        }
    }
    if (act) {
        #pragma unroll
        for (int i = 0; i < 8; i++)
            g_part[((size_t)kg * Ntot + n0 + rg * 8 + i) * KD + j] = acc[i];
    }
}

// ---------------------------------------------------------------------------
// Kernel C: per-batch epilogue — reduce partials + elu -> keys, multihead
// attention mixer, head weights, V, q_tot, attn output, alpha scatter.
// ---------------------------------------------------------------------------
__global__ __launch_bounds__(128) void kC(const float* __restrict__ aq,
                                          const float* __restrict__ states,
                                          const float* __restrict__ Wq,
                                          const float* __restrict__ Wk,
                                          const float* __restrict__ Wv1,
                                          const float* __restrict__ bv1,
                                          const float* __restrict__ Wv2,
                                          const float* __restrict__ bv2,
                                          const float* __restrict__ Ww1,
                                          const float* __restrict__ bw1,
                                          const float* __restrict__ Ww2,
                                          const float* __restrict__ bw2,
                                          float* __restrict__ dout) {
    int b = blockIdx.x, t = threadIdx.x;
    __shared__ float st_s[SD];
    __shared__ float keys_s[NA][KD];
    __shared__ float kvec[NA][NU];
    __shared__ float q_s[NU];
    __shared__ float hid[64], hv[32];
    __shared__ float hw_s[NH], v_s;
    __shared__ float outh[NH];

    for (int i = t; i < SD; i += 128) st_s[i] = states[(size_t)b * SD + i];

    // reduce hypernet partials over 5 k-groups, apply elu
    for (int idx = t; idx < NA * KD; idx += 128) {
        int a = idx / KD, j = idx % KD;
        float s = 0.f;
        #pragma unroll
        for (int kg = 0; kg < 5; kg++)
            s += g_part[((size_t)kg * Ntot + b * NA + a) * KD + j];
        keys_s[a][j] = (s > 0.f) ? s : expm1f(s);
    }
    __syncthreads();

    // kvec = keys @ Wk   (8x32)
    for (int idx = t; idx < NA * NU; idx += 128) {
        int a = idx / NU, u = idx % NU;
        float s = 0.f;
        #pragma unroll 5
        for (int j = 0; j < KD; j++) s += keys_s[a][j] * Wk[j * NU + u];
        kvec[a][u] = s;
    }
    // small state MLPs split across threads
    if (t < NU) {
        float s = 0.f;
        for (int o = 0; o < SD; o++) s += st_s[o] * Wq[o * NU + t];
        q_s[t] = s;
    } else if (t < 96) {
        int x = t - 32;
        float s = bw1[x];
        for (int o = 0; o < SD; o++) s += st_s[o] * Ww1[o * 64 + x];
        hid[x] = fmaxf(s, 0.f);
    } else {
        int x = t - 96;
        float s = bv1[x];
        for (int o = 0; o < SD; o++) s += st_s[o] * Wv1[o * NU + x];
        hv[x] = fmaxf(s, 0.f);
    }
    __syncthreads();

    if (t < NH) {
        float s = bw2[t];
        #pragma unroll
        for (int x = 0; x < 64; x++) s += hid[x] * Ww2[x * NH + t];
        hw_s[t] = s * s;
    } else if (t == NH) {
        float s = bv2[0];
        #pragma unroll
        for (int x = 0; x < 32; x++) s += hv[x] * Wv2[x];
        v_s = s;
    }
    __syncthreads();

    // attention per head + attn output + weighted head sum
    if (t < NH) {
        int hh = t;
        float sc[NA]; float m = -1e30f;
        #pragma unroll
        for (int a = 0; a < NA; a++) {
            float s = 0.f;
            #pragma unroll
            for (int dd = 0; dd < 8; dd++)
                s += q_s[hh * 8 + dd] * kvec[a][hh * 8 + dd];
            s *= 0.35355339059327373f;   // 1/sqrt(8)
            sc[a] = s; m = fmaxf(m, s);
        }
        float sum = 0.f;
        #pragma unroll
        for (int a = 0; a < NA; a++) { sc[a] = expf(sc[a] - m); sum += sc[a]; }
        float inv = 1.f / sum;
        float oh = 0.f;
        #pragma unroll
        for (int a = 0; a < NA; a++) {
            float at = sc[a] * inv;
            dout[OUT_ATTN + b * 32 + hh * 8 + a] = at;
            oh += at * aq[b * NA + a];
        }
        outh[hh] = oh * hw_s[hh];
    }
    __syncthreads();
    if (t == 0) dout[b] = outh[0] + outh[1] + outh[2] + outh[3] + v_s;

    // scatter alpha into the (already zeroed) dense matrix
    for (int idx = t; idx < 256; idx += 128) {
        int i = idx >> 5, j = (idx >> 2) & 7, hh = idx & 3;
        dout[OUT_DENSE +
             (((size_t)(b * NA + i)) * Ntot + b * NA + j) * NH + hh] =
            g_alpha[b * 256 + idx];
    }
}

// ---------------------------------------------------------------------------
extern "C" void kernel_launch(void* const* d_in, const int* in_sizes, int n_in,
                              void* d_out, int out_size) {
    const float* aq     = (const float*)d_in[0];
    const float* obs    = (const float*)d_in[1];
    const float* states = (const float*)d_in[2];
    // d_in[3] = edge_index (deterministic fully-connected graph; unused)
    const float* Wg   = (const float*)d_in[4];
    const float* bg   = (const float*)d_in[5];
    const float* asrc = (const float*)d_in[6];
    const float* adst = (const float*)d_in[7];
    const float* Wh   = (const float*)d_in[8];
    const float* bh   = (const float*)d_in[9];
    const float* Wq   = (const float*)d_in[10];
    const float* Wk   = (const float*)d_in[11];
    const float* Wv1  = (const float*)d_in[12];
    const float* bv1  = (const float*)d_in[13];
    const float* Wv2  = (const float*)d_in[14];
    const float* bv2  = (const float*)d_in[15];
    const float* Ww1  = (const float*)d_in[16];
    const float* bw1  = (const float*)d_in[17];
    const float* Ww2  = (const float*)d_in[18];
    const float* bw2  = (const float*)d_in[19];
    float* out = (float*)d_out;

    kA<<<Bsz, 256>>>(aq, obs, Wg, bg, asrc, adst);
    kB<<<640, TBB>>>(obs, Wh, bh, out);
    kC<<<Bsz, 128>>>(aq, states, Wq, Wk, Wv1, bv1, Wv2, bv2,
                     Ww1, bw1, Ww2, bw2, out);
}

// round 2
// speedup vs baseline: 1.3488x; 1.3488x over previous
#include <cuda_runtime.h>
#include <math.h>

// Problem constants
#define Bsz   512
#define NA    8
#define OB    160
#define SD    256
#define NH    4
#define GD    64
#define KD    65
#define NU    32
#define Ntot  4096
#define KDSQ  4225

// Output layout (flat concat, fp32):
//   [0,512) q_tot+v | [512,16896) attn | [16896,67125760) gnn_weight_matrics
#define OUT_ATTN  512
#define OUT_DENSE 16896
#define DENSE_F4  16777216ULL

// kB geometry
#define NTILES 64        // n-tiles of 64 rows
#define TMB    64        // rows per tile
#define NKG    13        // k groups
#define KPG    5         // k per group
#define TBB    288       // threads
#define NACT   264       // 8 rowgroups x 33 colpairs
#define WCH    40        // o-chunk rows
#define WPITCH 66        // padded W cols
#define PPITCH 66        // padded g_part cols
#define GRIDB  (NTILES * NKG)   // 832

typedef unsigned long long ull;

#define FMA2(c, a, b) asm("fma.rn.f32x2 %0, %1, %2, %0;" : "+l"(c) : "l"(a), "l"(b))
#define PACK2(d, x)   asm("mov.b64 %0, {%1, %1};" : "=l"(d) : "f"(x))

// Scratch
__device__ float g_keys_pre[Ntot * KD];                    // [n][65]
__device__ float g_alpha[Bsz * NA * NA * NH];              // [b][i][j][h]
__device__ float g_part[NKG * Ntot * PPITCH];              // [kg][n][66]

// ---------------------------------------------------------------------------
// Kernel A: GAT for 8 batches per block (grid 64, 256 threads).
// ---------------------------------------------------------------------------
__global__ __launch_bounds__(256) void kA(const float* __restrict__ aq,
                                          const float* __restrict__ obs,
                                          const float* __restrict__ Wg,
                                          const float* __restrict__ bg,
                                          const float* __restrict__ asrc,
                                          const float* __restrict__ adst) {
    __shared__ float buf[10240];          // obsT[160][64] -> h_s[64][64] + al[2048]
    __shared__ float ssd[2][8][8][4];     // src/dst scores
    __shared__ float aw_s[8][8][8];       // head-summed alpha

    int t = threadIdx.x;
    int n0 = blockIdx.x * 64;
    float* obsT = buf;

    // stage obs transposed: obsT[o][aa]
    for (int idx = t; idx < 40 * 64; idx += 256) {
        int aa = idx & 63, o4 = idx >> 6;
        float4 v = *(const float4*)(obs + (size_t)(n0 + aa) * OB + o4 * 4);
        obsT[(o4 * 4 + 0) * 64 + aa] = v.x;
        obsT[(o4 * 4 + 1) * 64 + aa] = v.y;
        obsT[(o4 * 4 + 2) * 64 + aa] = v.z;
        obsT[(o4 * 4 + 3) * 64 + aa] = v.w;
    }
    __syncthreads();

    // h = obs @ W_gnn + b : thread = (agent group of 16, g)
    int g = t & 63, ag = t >> 6;
    float h[16];
    {
        float b0 = bg[g];
        #pragma unroll
        for (int i = 0; i < 16; i++) h[i] = b0;
    }
    for (int o = 0; o < OB; o++) {
        float w = Wg[o * GD + g];
        const float4* op = (const float4*)&obsT[o * 64 + ag * 16];
        float4 x0 = op[0], x1 = op[1], x2 = op[2], x3 = op[3];
        h[0]  += x0.x * w; h[1]  += x0.y * w; h[2]  += x0.z * w; h[3]  += x0.w * w;
        h[4]  += x1.x * w; h[5]  += x1.y * w; h[6]  += x1.z * w; h[7]  += x1.w * w;
        h[8]  += x2.x * w; h[9]  += x2.y * w; h[10] += x2.z * w; h[11] += x2.w * w;
        h[12] += x3.x * w; h[13] += x3.y * w; h[14] += x3.z * w; h[15] += x3.w * w;
    }
    __syncthreads();
    float* h_s = buf;                      // [64][64], reuses obsT space
    #pragma unroll
    for (int i = 0; i < 16; i++) h_s[(ag * 16 + i) * 64 + g] = h[i];
    __syncthreads();

    // src/dst scores: 512 dots of length 64
    for (int rep = 0; rep < 2; rep++) {
        int id = rep * 256 + t;
        int aa = id >> 3, hh = (id >> 1) & 3, sd = id & 1;
        const float* av = (sd ? adst : asrc) + hh * GD;
        float acc = 0.f;
        #pragma unroll 8
        for (int gg = 0; gg < GD; gg++) acc += h_s[aa * 64 + gg] * av[gg];
        ssd[sd][aa >> 3][aa & 7][hh] = acc;
    }
    __syncthreads();

    // alpha: one (bb, dst j, head) per thread
    float* al = buf + 4096;                // [bb][i][j][hh] = 2048 floats
    {
        int bb = t >> 5, j = (t >> 2) & 7, hh = t & 3;
        float e[NA]; float m = -1e30f;
        #pragma unroll
        for (int i = 0; i < NA; i++) {
            if (i == j) { e[i] = -1e30f; continue; }
            float x = ssd[0][bb][i][hh] + ssd[1][bb][j][hh];
            x = x > 0.f ? x : 0.2f * x;
            e[i] = x; m = fmaxf(m, x);
        }
        float s = 0.f;
        #pragma unroll
        for (int i = 0; i < NA; i++) {
            float ex = (i == j) ? 0.f : expf(e[i] - m);
            e[i] = ex; s += ex;
        }
        float inv = 1.f / (s + 1e-16f);
        #pragma unroll
        for (int i = 0; i < NA; i++) al[((bb * 8 + i) * 8 + j) * 4 + hh] = e[i] * inv;
    }
    __syncthreads();

    // dump alpha + head-summed weights
    for (int idx = t; idx < 2048; idx += 256)
        g_alpha[(size_t)blockIdx.x * 2048 + idx] = al[idx];
    for (int rep = 0; rep < 2; rep++) {
        int id = rep * 256 + t;
        int bb = id >> 6, i = (id >> 3) & 7, j = id & 7;
        const float* a4 = &al[((bb * 8 + i) * 8 + j) * 4];
        aw_s[bb][i][j] = a4[0] + a4[1] + a4[2] + a4[3];
    }
    __syncthreads();

    // agg + relu -> keys_pre
    #pragma unroll
    for (int ii = 0; ii < 16; ii++) {
        int aa = ag * 16 + ii, bb = aa >> 3, j = aa & 7;
        float acc = 0.f;
        #pragma unroll
        for (int i = 0; i < NA; i++)
            acc += h_s[(bb * 8 + i) * 64 + g] * aw_s[bb][i][j];
        g_keys_pre[(size_t)(n0 + aa) * KD + 1 + g] = fmaxf(0.25f * acc, 0.f);
    }
    if (g == 0) {
        #pragma unroll
        for (int ii = 0; ii < 16; ii++)
            g_keys_pre[(size_t)(n0 + ag * 16 + ii) * KD] = aq[n0 + ag * 16 + ii];
    }
}

// ---------------------------------------------------------------------------
// Kernel B: hypernet GEMM, packed f32x2, cp.async double-buffered W staging,
// interleaved zero-fill of dense output.
// ---------------------------------------------------------------------------
__device__ __forceinline__ void stageW(const float* __restrict__ Wh, float* dst,
                                       int k, int o0, int t) {
    for (int idx = t; idx < WCH * KD; idx += TBB) {
        int o = idx / KD, j = idx - o * KD;
        unsigned sa = (unsigned)__cvta_generic_to_shared(dst + o * WPITCH + j);
        const float* src = Wh + (size_t)(o0 + o) * KDSQ + k * KD + j;
        asm volatile("cp.async.ca.shared.global [%0], [%1], 4;" :: "r"(sa), "l"(src));
    }
}

__global__ __launch_bounds__(TBB, 2) void kB(const float* __restrict__ obs,
                                             const float* __restrict__ Wh,
                                             const float* __restrict__ bh,
                                             float* __restrict__ dout) {
    extern __shared__ float sm[];
    float* obsT = sm;                         // [160][64]
    float* Wb   = sm + 160 * 64;              // [2][40][66]
    float* keys = Wb + 2 * WCH * WPITCH;      // [64][5]

    int nt = blockIdx.x % NTILES;
    int kg = blockIdx.x / NTILES;
    int n0 = nt * TMB;
    int k0 = kg * KPG;
    int t = threadIdx.x;
    int rg = t / 33, cp = t - rg * 33;        // rowgroup(8 rows), colpair
    bool act = (t < NACT);

    // zero-fill state
    float4* zp = (float4*)(dout + OUT_DENSE);
    unsigned long long zi = (unsigned long long)blockIdx.x * TBB + t;
    const unsigned long long zstride = (unsigned long long)GRIDB * TBB;

    // kick off W stage 0 ASAP
    stageW(Wh, Wb, k0, 0, t);
    asm volatile("cp.async.commit_group;");

    // stage obs transposed (once)
    for (int idx = t; idx < 40 * 64; idx += TBB) {
        int r = idx & 63, o4 = idx >> 6;
        float4 v = *(const float4*)(obs + (size_t)(n0 + r) * OB + o4 * 4);
        obsT[(o4 * 4 + 0) * 64 + r] = v.x;
        obsT[(o4 * 4 + 1) * 64 + r] = v.y;
        obsT[(o4 * 4 + 2) * 64 + r] = v.z;
        obsT[(o4 * 4 + 3) * 64 + r] = v.w;
    }
    // stage key weights
    for (int idx = t; idx < TMB * KPG; idx += TBB) {
        int r = idx / KPG, kk = idx - r * KPG;
        keys[idx] = g_keys_pre[(size_t)(n0 + r) * KD + k0 + kk];
    }
    // zero the W pad column (both buffers)
    for (int idx = t; idx < 2 * WCH; idx += TBB)
        Wb[idx * WPITCH + KD] = 0.f;

    ull c0[4], c1[4];
    float2 acc0[4], acc1[4];
    #pragma unroll
    for (int p = 0; p < 4; p++) {
        c0[p] = 0ULL; c1[p] = 0ULL;
        acc0[p] = make_float2(0.f, 0.f);
        acc1[p] = make_float2(0.f, 0.f);
    }

    for (int kk = 0; kk < KPG; kk++) {
        int k = k0 + kk;
        for (int ch = 0; ch < 4; ch++) {
            int s = kk * 4 + ch, nxt = s + 1;
            if (nxt < 20) {
                stageW(Wh, Wb + (nxt & 1) * (WCH * WPITCH),
                       k0 + (nxt >> 2), (nxt & 3) * WCH, t);
                asm volatile("cp.async.commit_group;");
                asm volatile("cp.async.wait_group 1;");
            } else {
                asm volatile("cp.async.wait_group 0;");
            }
            __syncthreads();

            if (act) {
                const float* ob = obsT + (ch * WCH) * 64 + rg * 8;
                const float* wc = Wb + (s & 1) * (WCH * WPITCH) + 2 * cp;
                #pragma unroll 4
                for (int oo = 0; oo < WCH; oo++) {
                    ulonglong2 A = *(const ulonglong2*)(ob);
                    ulonglong2 Bv = *(const ulonglong2*)(ob + 4);
                    float2 w2 = *(const float2*)(wc);
                    ull w0, w1;
                    PACK2(w0, w2.x); PACK2(w1, w2.y);
                    FMA2(c0[0], A.x,  w0); FMA2(c0[1], A.y,  w0);
                    FMA2(c0[2], Bv.x, w0); FMA2(c0[3], Bv.y, w0);
                    FMA2(c1[0], A.x,  w1); FMA2(c1[1], A.y,  w1);
                    FMA2(c1[2], Bv.x, w1); FMA2(c1[3], Bv.y, w1);
                    ob += 64; wc += WPITCH;
                }
            }
            // hidden zero-fill of dense output
            #pragma unroll
            for (int z = 0; z < 4; z++) {
                if (zi < DENSE_F4) zp[zi] = make_float4(0.f, 0.f, 0.f, 0.f);
                zi += zstride;
            }
            __syncthreads();
        }
        if (act) {
            int j0 = 2 * cp, j1 = 2 * cp + 1;
            float bias0 = bh[k * KD + j0];
            float bias1 = (j1 < KD) ? bh[k * KD + j1] : 0.f;
            #pragma unroll
            for (int p = 0; p < 4; p++) {
                float2 v0 = *(float2*)&c0[p];
                float2 v1 = *(float2*)&c1[p];
                float ky0 = keys[(rg * 8 + 2 * p) * KPG + kk];
                float ky1 = keys[(rg * 8 + 2 * p + 1) * KPG + kk];
                acc0[p].x += ky0 * fabsf(v0.x + bias0);
                acc0[p].y += ky1 * fabsf(v0.y + bias0);
                acc1[p].x += ky0 * fabsf(v1.x + bias1);
                acc1[p].y += ky1 * fabsf(v1.y + bias1);
                c0[p] = 0ULL; c1[p] = 0ULL;
            }
        }
    }

    if (act) {
        size_t base = (size_t)kg * Ntot * PPITCH + (size_t)n0 * PPITCH + 2 * cp;
        #pragma unroll
        for (int p = 0; p < 4; p++) {
            int r0 = rg * 8 + 2 * p;
            *(float2*)&g_part[base + (size_t)r0 * PPITCH] =
                make_float2(acc0[p].x, acc1[p].x);
            *(float2*)&g_part[base + (size_t)(r0 + 1) * PPITCH] =
                make_float2(acc0[p].y, acc1[p].y);
        }
    }
}

// ---------------------------------------------------------------------------
// Kernel C: reduce partials + elu, attention mixer, head weights, V, scatter.
// ---------------------------------------------------------------------------
__global__ __launch_bounds__(128) void kC(const float* __restrict__ aq,
                                          const float* __restrict__ states,
                                          const float* __restrict__ Wq,
                                          const float* __restrict__ Wk,
                                          const float* __restrict__ Wv1,
                                          const float* __restrict__ bv1,
                                          const float* __restrict__ Wv2,
                                          const float* __restrict__ bv2,
                                          const float* __restrict__ Ww1,
                                          const float* __restrict__ bw1,
                                          const float* __restrict__ Ww2,
                                          const float* __restrict__ bw2,
                                          float* __restrict__ dout) {
    int b = blockIdx.x, t = threadIdx.x;
    __shared__ float st_s[SD];
    __shared__ float keys_s[NA][KD];
    __shared__ float kvec[NA][NU];
    __shared__ float q_s[NU];
    __shared__ float hid[64], hv[32];
    __shared__ float hw_s[NH], v_s;
    __shared__ float outh[NH];

    for (int i = t; i < SD; i += 128) st_s[i] = states[(size_t)b * SD + i];

    for (int idx = t; idx < NA * KD; idx += 128) {
        int a = idx / KD, j = idx - (idx / KD) * KD;
        size_t base = (size_t)(b * NA + a) * PPITCH + j;
        float s = 0.f;
        #pragma unroll
        for (int kg = 0; kg < NKG; kg++)
            s += g_part[(size_t)kg * Ntot * PPITCH + base];
        keys_s[a][j] = (s > 0.f) ? s : expm1f(s);
    }
    __syncthreads();

    for (int idx = t; idx < NA * NU; idx += 128) {
        int a = idx / NU, u = idx & 31;
        float s = 0.f;
        #pragma unroll 5
        for (int j = 0; j < KD; j++) s += keys_s[a][j] * Wk[j * NU + u];
        kvec[a][u] = s;
    }
    if (t < NU) {
        float s = 0.f;
        for (int o = 0; o < SD; o++) s += st_s[o] * Wq[o * NU + t];
        q_s[t] = s;
    } else if (t < 96) {
        int x = t - 32;
        float s = bw1[x];
        for (int o = 0; o < SD; o++) s += st_s[o] * Ww1[o * 64 + x];
        hid[x] = fmaxf(s, 0.f);
    } else {
        int x = t - 96;
        float s = bv1[x];
        for (int o = 0; o < SD; o++) s += st_s[o] * Wv1[o * NU + x];
        hv[x] = fmaxf(s, 0.f);
    }
    __syncthreads();

    if (t < NH) {
        float s = bw2[t];
        #pragma unroll
        for (int x = 0; x < 64; x++) s += hid[x] * Ww2[x * NH + t];
        hw_s[t] = s * s;
    } else if (t == NH) {
        float s = bv2[0];
        #pragma unroll
        for (int x = 0; x < 32; x++) s += hv[x] * Wv2[x];
        v_s = s;
    }
    __syncthreads();

    if (t < NH) {
        int hh = t;
        float sc[NA]; float m = -1e30f;
        #pragma unroll
        for (int a = 0; a < NA; a++) {
            float s = 0.f;
            #pragma unroll
            for (int dd = 0; dd < 8; dd++)
                s += q_s[hh * 8 + dd] * kvec[a][hh * 8 + dd];
            s *= 0.35355339059327373f;
            sc[a] = s; m = fmaxf(m, s);
        }
        float sum = 0.f;
        #pragma unroll
        for (int a = 0; a < NA; a++) { sc[a] = expf(sc[a] - m); sum += sc[a]; }
        float inv = 1.f / sum;
        float oh = 0.f;
        #pragma unroll
        for (int a = 0; a < NA; a++) {
            float at = sc[a] * inv;
            dout[OUT_ATTN + b * 32 + hh * 8 + a] = at;
            oh += at * aq[b * NA + a];
        }
        outh[hh] = oh * hw_s[hh];
    }
    __syncthreads();
    if (t == 0) dout[b] = outh[0] + outh[1] + outh[2] + outh[3] + v_s;

    for (int idx = t; idx < 256; idx += 128) {
        int i = idx >> 5, j = (idx >> 2) & 7, hh = idx & 3;
        dout[OUT_DENSE +
             (((size_t)(b * NA + i)) * Ntot + b * NA + j) * NH + hh] =
            g_alpha[b * 256 + idx];
    }
}

// ---------------------------------------------------------------------------
extern "C" void kernel_launch(void* const* d_in, const int* in_sizes, int n_in,
                              void* d_out, int out_size) {
    const float* aq     = (const float*)d_in[0];
    const float* obs    = (const float*)d_in[1];
    const float* states = (const float*)d_in[2];
    // d_in[3] = edge_index (deterministic; unused)
    const float* Wg   = (const float*)d_in[4];
    const float* bg   = (const float*)d_in[5];
    const float* asrc = (const float*)d_in[6];
    const float* adst = (const float*)d_in[7];
    const float* Wh   = (const float*)d_in[8];
    const float* bh   = (const float*)d_in[9];
    const float* Wq   = (const float*)d_in[10];
    const float* Wk   = (const float*)d_in[11];
    const float* Wv1  = (const float*)d_in[12];
    const float* bv1  = (const float*)d_in[13];
    const float* Wv2  = (const float*)d_in[14];
    const float* bv2  = (const float*)d_in[15];
    const float* Ww1  = (const float*)d_in[16];
    const float* bw1  = (const float*)d_in[17];
    const float* Ww2  = (const float*)d_in[18];
    const float* bw2  = (const float*)d_in[19];
    float* out = (float*)d_out;

    const int kb_smem = (160 * 64 + 2 * WCH * WPITCH + TMB * KPG) * 4;
    cudaFuncSetAttribute(kB, cudaFuncAttributeMaxDynamicSharedMemorySize, kb_smem);

    kA<<<64, 256>>>(aq, obs, Wg, bg, asrc, adst);
    kB<<<GRIDB, TBB, kb_smem>>>(obs, Wh, bh, out);
    kC<<<Bsz, 128>>>(aq, states, Wq, Wk, Wv1, bv1, Wv2, bv2,
                     Ww1, bw1, Ww2, bw2, out);
}

// round 3
// speedup vs baseline: 1.4735x; 1.0925x over previous
#include <cuda_runtime.h>
#include <math.h>

// Problem constants
#define Bsz   512
#define NA    8
#define OB    160
#define SD    256
#define NH    4
#define GD    64
#define KD    65
#define NU    32
#define Ntot  4096
#define KDSQ  4225

// Output layout (flat concat, fp32)
#define OUT_ATTN  512
#define OUT_DENSE 16896
#define DENSE_F4  16777216ULL

// kB geometry: block = 256 rows x 65 cols(pad 72) x one k.  grid = 65*16
#define TMB    256
#define TKC    40          // K-chunk (o) per stage
#define NC     72          // padded col count
#define TBB    288         // 32 rowgroups x 9 colgroups
#define GRIDB  (65 * 16)   // 1040
#define PP     68          // g_part pitch (16B-aligned rows)

typedef unsigned long long ull;

#define FMA2(c, a, b) asm("fma.rn.f32x2 %0, %1, %2, %0;" : "+l"(c) : "l"(a), "l"(b))
#define PACK2(d, x)   asm("mov.b64 %0, {%1, %1};" : "=l"(d) : "f"(x))
#define CPA16(dst, src) asm volatile("cp.async.cg.shared.global [%0], [%1], 16;" :: "r"(dst), "l"(src))
#define CPA4(dst, src)  asm volatile("cp.async.ca.shared.global [%0], [%1], 4;"  :: "r"(dst), "l"(src))

// Scratch
__device__ float g_keys_pre[Ntot * KD];            // [n][65]
__device__ float g_alpha[Bsz * 256];               // [b][i][j][h]
__device__ float g_obsT[OB * Ntot];                // [o][n]  (A transposed)
__device__ float g_part[(size_t)KD * Ntot * PP];   // [k][n][68]

// ---------------------------------------------------------------------------
// Kernel A: GAT, 2 batches (16 agents) per block, grid 256.
// Also emits g_obsT (transposed obs) for kB's coalesced A staging.
// ---------------------------------------------------------------------------
__global__ __launch_bounds__(256) void kA(const float* __restrict__ aq,
                                          const float* __restrict__ obs,
                                          const float* __restrict__ Wg,
                                          const float* __restrict__ bg,
                                          const float* __restrict__ asrc,
                                          const float* __restrict__ adst) {
    __shared__ float obs_s[16][OB];
    __shared__ float h_s[16][GD];
    __shared__ float sc_s[2][16][NH];
    __shared__ float al[2][8][8][NH];
    __shared__ float aw[2][8][8];

    int t = threadIdx.x;
    int n0 = blockIdx.x * 16;

    // load obs (contiguous float4)
    {
        const float4* src = (const float4*)(obs + (size_t)n0 * OB);
        float4* dst = (float4*)obs_s;
        for (int idx = t; idx < 16 * OB / 4; idx += 256) dst[idx] = src[idx];
    }
    __syncthreads();

    // transposed obs to global (for kB)
    for (int idx = t; idx < 16 * OB; idx += 256) {
        int o = idx >> 4, r = idx & 15;
        g_obsT[(size_t)o * Ntot + n0 + r] = obs_s[r][o];
    }

    // h = obs @ W_gnn + b : thread = (row r, col-quad gq)
    {
        int r = t >> 4, gq = t & 15;
        float4 b4 = *(const float4*)(bg + gq * 4);
        float h0 = b4.x, h1 = b4.y, h2 = b4.z, h3 = b4.w;
        #pragma unroll 8
        for (int o = 0; o < OB; o++) {
            float x = obs_s[r][o];
            float4 w = *(const float4*)(Wg + o * GD + gq * 4);
            h0 += x * w.x; h1 += x * w.y; h2 += x * w.z; h3 += x * w.w;
        }
        h_s[r][gq * 4 + 0] = h0; h_s[r][gq * 4 + 1] = h1;
        h_s[r][gq * 4 + 2] = h2; h_s[r][gq * 4 + 3] = h3;
    }
    __syncthreads();

    // src/dst scores: 16 agents x 4 heads x 2
    if (t < 128) {
        int a = t >> 3, hh = (t >> 1) & 3, sd = t & 1;
        const float* av = (sd ? adst : asrc) + hh * GD;
        float acc = 0.f;
        #pragma unroll 8
        for (int g = 0; g < GD; g++) acc += h_s[a][g] * av[g];
        sc_s[sd][a][hh] = acc;
    }
    __syncthreads();

    // alpha per (local batch, dst j, head)
    if (t < 64) {
        int bbx = t >> 5, j = (t >> 2) & 7, hh = t & 3;
        float e[NA]; float m = -1e30f;
        #pragma unroll
        for (int i = 0; i < NA; i++) {
            if (i == j) { e[i] = -1e30f; continue; }
            float x = sc_s[0][bbx * 8 + i][hh] + sc_s[1][bbx * 8 + j][hh];
            x = x > 0.f ? x : 0.2f * x;
            e[i] = x; m = fmaxf(m, x);
        }
        float s = 0.f;
        #pragma unroll
        for (int i = 0; i < NA; i++) {
            float ex = (i == j) ? 0.f : expf(e[i] - m);
            e[i] = ex; s += ex;
        }
        float inv = 1.f / (s + 1e-16f);
        #pragma unroll
        for (int i = 0; i < NA; i++) al[bbx][i][j][hh] = e[i] * inv;
    }
    __syncthreads();

    // dump alpha + head-summed weights
    for (int idx = t; idx < 512; idx += 256)
        g_alpha[(size_t)blockIdx.x * 512 + idx] = ((const float*)al)[idx];
    if (t < 128) {
        int bbx = t >> 6, i = (t >> 3) & 7, j = t & 7;
        const float* a4 = &al[bbx][i][j][0];
        aw[bbx][i][j] = a4[0] + a4[1] + a4[2] + a4[3];
    }
    __syncthreads();

    // agg + relu -> keys_pre
    for (int idx = t; idx < 16 * GD; idx += 256) {
        int aa = idx >> 6, g = idx & 63;
        int bbx = aa >> 3, j = aa & 7;
        float acc = 0.f;
        #pragma unroll
        for (int i = 0; i < NA; i++)
            acc += h_s[bbx * 8 + i][g] * aw[bbx][i][j];
        g_keys_pre[(size_t)(n0 + aa) * KD + 1 + g] = fmaxf(0.25f * acc, 0.f);
        if (g == 0)
            g_keys_pre[(size_t)(n0 + aa) * KD] = aq[n0 + aa];
    }
}

// ---------------------------------------------------------------------------
// Kernel B: hypernet GEMM, 8x8 thread tile with f32x2 FMAs, cp.async
// double-buffered A/B staging, interleaved streaming zero-fill.
// ---------------------------------------------------------------------------
__device__ __forceinline__ void stageA(float* As, int o0, int n0, int t) {
    for (int idx = t; idx < TKC * 64; idx += TBB) {      // float4 units
        int o = idx >> 6, q = idx & 63;
        unsigned sa = (unsigned)__cvta_generic_to_shared(As + o * TMB + q * 4);
        const float* src = g_obsT + (size_t)(o0 + o) * Ntot + n0 + q * 4;
        CPA16(sa, src);
    }
}
__device__ __forceinline__ void stageB(const float* __restrict__ Wh, float* Bs,
                                       int o0, int k, int t) {
    for (int idx = t; idx < TKC * NC; idx += TBB) {
        int o = idx / NC, j = idx - o * NC;
        int jc = j > 64 ? 64 : j;
        unsigned sa = (unsigned)__cvta_generic_to_shared(Bs + o * NC + j);
        const float* src = Wh + (size_t)(o0 + o) * KDSQ + k * KD + jc;
        CPA4(sa, src);
    }
}

__global__ __launch_bounds__(TBB, 2) void kB(const float* __restrict__ Wh,
                                             const float* __restrict__ bh,
                                             float* __restrict__ dout) {
    extern __shared__ float sm[];
    float* As = sm;                       // [2][40][256]
    float* Bs = sm + 2 * TKC * TMB;       // [2][40][72]
    float* keys_s = Bs + 2 * TKC * NC;    // [256]

    int bx = blockIdx.x;
    int k  = bx >> 4;                     // k-major: 16 rowtiles share W slab
    int n0 = (bx & 15) * TMB;
    int t = threadIdx.x;
    int rg = t / 9, cg = t - rg * 9;      // 32 x 9

    // zero-fill state (streaming stores, evict-first)
    float4* zp = (float4*)(dout + OUT_DENSE);
    unsigned long long zi = (unsigned long long)bx * TBB + t;
    const unsigned long long zstride = (unsigned long long)GRIDB * TBB;
    const float4 zero4 = make_float4(0.f, 0.f, 0.f, 0.f);

    stageA(As, 0, n0, t);
    stageB(Wh, Bs, 0, k, t);
    asm volatile("cp.async.commit_group;");

    if (t < TMB) keys_s[t] = g_keys_pre[(size_t)(n0 + t) * KD + k];

    ull c[4][8];
    #pragma unroll
    for (int p = 0; p < 4; p++)
        #pragma unroll
        for (int j = 0; j < 8; j++) c[p][j] = 0ULL;

    for (int ch = 0; ch < 4; ch++) {
        if (ch < 3) {
            int nb = (ch + 1) & 1;
            stageA(As + nb * TKC * TMB, (ch + 1) * TKC, n0, t);
            stageB(Wh, Bs + nb * TKC * NC, (ch + 1) * TKC, k, t);
            asm volatile("cp.async.commit_group;");
            asm volatile("cp.async.wait_group 1;");
        } else {
            asm volatile("cp.async.wait_group 0;");
        }
        __syncthreads();

        const float* Ap = As + (ch & 1) * TKC * TMB + rg * 8;
        const float* Bp = Bs + (ch & 1) * TKC * NC + cg * 8;
        #pragma unroll 2
        for (int o = 0; o < TKC; o++) {
            ulonglong2 A0 = *(const ulonglong2*)Ap;
            ulonglong2 A1 = *(const ulonglong2*)(Ap + 4);
            float4 b0 = *(const float4*)Bp;
            float4 b1 = *(const float4*)(Bp + 4);
            ull w;
            PACK2(w, b0.x);
            FMA2(c[0][0], A0.x, w); FMA2(c[1][0], A0.y, w);
            FMA2(c[2][0], A1.x, w); FMA2(c[3][0], A1.y, w);
            PACK2(w, b0.y);
            FMA2(c[0][1], A0.x, w); FMA2(c[1][1], A0.y, w);
            FMA2(c[2][1], A1.x, w); FMA2(c[3][1], A1.y, w);
            PACK2(w, b0.z);
            FMA2(c[0][2], A0.x, w); FMA2(c[1][2], A0.y, w);
            FMA2(c[2][2], A1.x, w); FMA2(c[3][2], A1.y, w);
            PACK2(w, b0.w);
            FMA2(c[0][3], A0.x, w); FMA2(c[1][3], A0.y, w);
            FMA2(c[2][3], A1.x, w); FMA2(c[3][3], A1.y, w);
            PACK2(w, b1.x);
            FMA2(c[0][4], A0.x, w); FMA2(c[1][4], A0.y, w);
            FMA2(c[2][4], A1.x, w); FMA2(c[3][4], A1.y, w);
            PACK2(w, b1.y);
            FMA2(c[0][5], A0.x, w); FMA2(c[1][5], A0.y, w);
            FMA2(c[2][5], A1.x, w); FMA2(c[3][5], A1.y, w);
            PACK2(w, b1.z);
            FMA2(c[0][6], A0.x, w); FMA2(c[1][6], A0.y, w);
            FMA2(c[2][6], A1.x, w); FMA2(c[3][6], A1.y, w);
            PACK2(w, b1.w);
            FMA2(c[0][7], A0.x, w); FMA2(c[1][7], A0.y, w);
            FMA2(c[2][7], A1.x, w); FMA2(c[3][7], A1.y, w);
            Ap += TMB; Bp += NC;
        }

        // hidden zero-fill (streaming, evict-first)
        #pragma unroll
        for (int z = 0; z < 15; z++) {
            if (zi < DENSE_F4) __stcs(&zp[zi], zero4);
            zi += zstride;
        }
        __syncthreads();
    }

    // epilogue: weighted-abs per element -> g_part[k][n][j]
    float bias[8];
    #pragma unroll
    for (int jj = 0; jj < 8; jj++) {
        int j = cg * 8 + jj;
        bias[jj] = bh[k * KD + (j > 64 ? 64 : j)];
    }
    float* gp = g_part + (size_t)k * Ntot * PP + (size_t)n0 * PP + cg * 8;
    #pragma unroll
    for (int p = 0; p < 4; p++) {
        int r0 = rg * 8 + 2 * p;
        float k0 = keys_s[r0], k1 = keys_s[r0 + 1];
        float v0[8], v1[8];
        #pragma unroll
        for (int jj = 0; jj < 8; jj++) {
            float2 cv = *(float2*)&c[p][jj];
            v0[jj] = k0 * fabsf(cv.x + bias[jj]);
            v1[jj] = k1 * fabsf(cv.y + bias[jj]);
        }
        float* p0 = gp + (size_t)r0 * PP;
        float* p1 = p0 + PP;
        if (cg < 8) {
            *(float4*)p0 = make_float4(v0[0], v0[1], v0[2], v0[3]);
            *(float4*)(p0 + 4) = make_float4(v0[4], v0[5], v0[6], v0[7]);
            *(float4*)p1 = make_float4(v1[0], v1[1], v1[2], v1[3]);
            *(float4*)(p1 + 4) = make_float4(v1[4], v1[5], v1[6], v1[7]);
        } else {
            p0[0] = v0[0];   // j == 64
            p1[0] = v1[0];
        }
    }
}

// ---------------------------------------------------------------------------
// Kernel C: reduce 65 k-partials + elu, attention mixer, head weights, V.
// ---------------------------------------------------------------------------
__global__ __launch_bounds__(128) void kC(const float* __restrict__ aq,
                                          const float* __restrict__ states,
                                          const float* __restrict__ Wq,
                                          const float* __restrict__ Wk,
                                          const float* __restrict__ Wv1,
                                          const float* __restrict__ bv1,
                                          const float* __restrict__ Wv2,
                                          const float* __restrict__ bv2,
                                          const float* __restrict__ Ww1,
                                          const float* __restrict__ bw1,
                                          const float* __restrict__ Ww2,
                                          const float* __restrict__ bw2,
                                          float* __restrict__ dout) {
    int b = blockIdx.x, t = threadIdx.x;
    __shared__ float st_s[SD];
    __shared__ float keys_s[NA][KD];
    __shared__ float kvec[NA][NU];
    __shared__ float q_s[NU];
    __shared__ float hid[64], hv[32];
    __shared__ float hw_s[NH], v_s;
    __shared__ float outh[NH];

    for (int i = t; i < SD; i += 128) st_s[i] = states[(size_t)b * SD + i];

    const size_t KSTR = (size_t)Ntot * PP;
    for (int idx = t; idx < NA * KD; idx += 128) {
        int a = idx / KD, j = idx - (idx / KD) * KD;
        const float* p = g_part + (size_t)(b * NA + a) * PP + j;
        float s = 0.f;
        #pragma unroll 13
        for (int kg = 0; kg < KD; kg++) s += p[(size_t)kg * KSTR];
        keys_s[a][j] = (s > 0.f) ? s : expm1f(s);
    }
    __syncthreads();

    for (int idx = t; idx < NA * NU; idx += 128) {
        int a = idx / NU, u = idx & 31;
        float s = 0.f;
        #pragma unroll 5
        for (int j = 0; j < KD; j++) s += keys_s[a][j] * Wk[j * NU + u];
        kvec[a][u] = s;
    }
    if (t < NU) {
        float s = 0.f;
        for (int o = 0; o < SD; o++) s += st_s[o] * Wq[o * NU + t];
        q_s[t] = s;
    } else if (t < 96) {
        int x = t - 32;
        float s = bw1[x];
        for (int o = 0; o < SD; o++) s += st_s[o] * Ww1[o * 64 + x];
        hid[x] = fmaxf(s, 0.f);
    } else {
        int x = t - 96;
        float s = bv1[x];
        for (int o = 0; o < SD; o++) s += st_s[o] * Wv1[o * NU + x];
        hv[x] = fmaxf(s, 0.f);
    }
    __syncthreads();

    if (t < NH) {
        float s = bw2[t];
        #pragma unroll
        for (int x = 0; x < 64; x++) s += hid[x] * Ww2[x * NH + t];
        hw_s[t] = s * s;
    } else if (t == NH) {
        float s = bv2[0];
        #pragma unroll
        for (int x = 0; x < 32; x++) s += hv[x] * Wv2[x];
        v_s = s;
    }
    __syncthreads();

    if (t < NH) {
        int hh = t;
        float sc[NA]; float m = -1e30f;
        #pragma unroll
        for (int a = 0; a < NA; a++) {
            float s = 0.f;
            #pragma unroll
            for (int dd = 0; dd < 8; dd++)
                s += q_s[hh * 8 + dd] * kvec[a][hh * 8 + dd];
            s *= 0.35355339059327373f;
            sc[a] = s; m = fmaxf(m, s);
        }
        float sum = 0.f;
        #pragma unroll
        for (int a = 0; a < NA; a++) { sc[a] = expf(sc[a] - m); sum += sc[a]; }
        float inv = 1.f / sum;
        float oh = 0.f;
        #pragma unroll
        for (int a = 0; a < NA; a++) {
            float at = sc[a] * inv;
            dout[OUT_ATTN + b * 32 + hh * 8 + a] = at;
            oh += at * aq[b * NA + a];
        }
        outh[hh] = oh * hw_s[hh];
    }
    __syncthreads();
    if (t == 0) dout[b] = outh[0] + outh[1] + outh[2] + outh[3] + v_s;

    for (int idx = t; idx < 256; idx += 128) {
        int i = idx >> 5, j = (idx >> 2) & 7, hh = idx & 3;
        dout[OUT_DENSE +
             (((size_t)(b * NA + i)) * Ntot + b * NA + j) * NH + hh] =
            g_alpha[b * 256 + idx];
    }
}

// ---------------------------------------------------------------------------
extern "C" void kernel_launch(void* const* d_in, const int* in_sizes, int n_in,
                              void* d_out, int out_size) {
    const float* aq     = (const float*)d_in[0];
    const float* obs    = (const float*)d_in[1];
    const float* states = (const float*)d_in[2];
    // d_in[3] = edge_index (deterministic; unused)
    const float* Wg   = (const float*)d_in[4];
    const float* bg   = (const float*)d_in[5];
    const float* asrc = (const float*)d_in[6];
    const float* adst = (const float*)d_in[7];
    const float* Wh   = (const float*)d_in[8];
    const float* bh   = (const float*)d_in[9];
    const float* Wq   = (const float*)d_in[10];
    const float* Wk   = (const float*)d_in[11];
    const float* Wv1  = (const float*)d_in[12];
    const float* bv1  = (const float*)d_in[13];
    const float* Wv2  = (const float*)d_in[14];
    const float* bv2  = (const float*)d_in[15];
    const float* Ww1  = (const float*)d_in[16];
    const float* bw1  = (const float*)d_in[17];
    const float* Ww2  = (const float*)d_in[18];
    const float* bw2  = (const float*)d_in[19];
    float* out = (float*)d_out;

    const int kb_smem = (2 * TKC * TMB + 2 * TKC * NC + TMB) * 4;
    static int configured = 0;
    cudaFuncSetAttribute(kB, cudaFuncAttributeMaxDynamicSharedMemorySize, kb_smem);
    (void)configured;

    kA<<<256, 256>>>(aq, obs, Wg, bg, asrc, adst);
    kB<<<GRIDB, TBB, kb_smem>>>(Wh, bh, out);
    kC<<<Bsz, 128>>>(aq, states, Wq, Wk, Wv1, bv1, Wv2, bv2,
                     Ww1, bw1, Ww2, bw2, out);
}

// round 4
// speedup vs baseline: 2.0302x; 1.3778x over previous
#include <cuda_runtime.h>
#include <math.h>

// Problem constants
#define Bsz   512
#define NA    8
#define OB    160
#define SD    256
#define NH    4
#define GD    64
#define KD    65
#define NU    32
#define Ntot  4096
#define KDSQ  4225

// Output layout (flat concat, fp32)
#define OUT_ATTN  512
#define OUT_DENSE 16896
#define DENSE_F4  16777216ULL

// kB geometry: block = 256 rows x 64 cols x one k.  grid = 65*16
#define TMB    256
#define TKC    40          // o-chunk per stage
#define NCB    64          // cols per block (pad-free)
#define TBB    256         // 32 rowgroups x 8 colgroups
#define GRIDB  (65 * 16)   // 1040
#define PP     68          // g_part pitch

typedef unsigned long long ull;

#define FMA2(c, a, b) asm("fma.rn.f32x2 %0, %1, %2, %0;" : "+l"(c) : "l"(a), "l"(b))
#define PACK2(d, x)   asm("mov.b64 %0, {%1, %1};" : "=l"(d) : "f"(x))
#define CPA16(dst, src) asm volatile("cp.async.cg.shared.global [%0], [%1], 16;" :: "r"(dst), "l"(src))
#define CPA4(dst, src)  asm volatile("cp.async.ca.shared.global [%0], [%1], 4;"  :: "r"(dst), "l"(src))

// Scratch
__device__ float g_keys_pre[Ntot * KD];            // [n][65]
__device__ float g_alpha[Bsz * 256];               // [b][i][j][h]
__device__ float g_obsT[OB * Ntot];                // [o][n]
__device__ float g_part[(size_t)KD * Ntot * PP];   // [k][n][68]

// ---------------------------------------------------------------------------
// Kernel A: GAT, 2 batches (16 agents) per block, grid 256.
// Also emits g_obsT (transposed obs) for kB's coalesced A staging.
// ---------------------------------------------------------------------------
__global__ __launch_bounds__(256) void kA(const float* __restrict__ aq,
                                          const float* __restrict__ obs,
                                          const float* __restrict__ Wg,
                                          const float* __restrict__ bg,
                                          const float* __restrict__ asrc,
                                          const float* __restrict__ adst) {
    __shared__ float obs_s[16][OB];
    __shared__ float h_s[16][GD];
    __shared__ float sc_s[2][16][NH];
    __shared__ float al[2][8][8][NH];
    __shared__ float aw[2][8][8];

    int t = threadIdx.x;
    int n0 = blockIdx.x * 16;

    {
        const float4* src = (const float4*)(obs + (size_t)n0 * OB);
        float4* dst = (float4*)obs_s;
        for (int idx = t; idx < 16 * OB / 4; idx += 256) dst[idx] = src[idx];
    }
    __syncthreads();

    for (int idx = t; idx < 16 * OB; idx += 256) {
        int o = idx >> 4, r = idx & 15;
        g_obsT[(size_t)o * Ntot + n0 + r] = obs_s[r][o];
    }

    // h = obs @ W_gnn + b : thread = (row r, col-quad gq)
    {
        int r = t >> 4, gq = t & 15;
        float4 b4 = *(const float4*)(bg + gq * 4);
        float h0 = b4.x, h1 = b4.y, h2 = b4.z, h3 = b4.w;
        #pragma unroll 8
        for (int o = 0; o < OB; o++) {
            float x = obs_s[r][o];
            float4 w = *(const float4*)(Wg + o * GD + gq * 4);
            h0 += x * w.x; h1 += x * w.y; h2 += x * w.z; h3 += x * w.w;
        }
        h_s[r][gq * 4 + 0] = h0; h_s[r][gq * 4 + 1] = h1;
        h_s[r][gq * 4 + 2] = h2; h_s[r][gq * 4 + 3] = h3;
    }
    __syncthreads();

    if (t < 128) {
        int a = t >> 3, hh = (t >> 1) & 3, sd = t & 1;
        const float* av = (sd ? adst : asrc) + hh * GD;
        float acc = 0.f;
        #pragma unroll 8
        for (int g = 0; g < GD; g++) acc += h_s[a][g] * av[g];
        sc_s[sd][a][hh] = acc;
    }
    __syncthreads();

    if (t < 64) {
        int bbx = t >> 5, j = (t >> 2) & 7, hh = t & 3;
        float e[NA]; float m = -1e30f;
        #pragma unroll
        for (int i = 0; i < NA; i++) {
            if (i == j) { e[i] = -1e30f; continue; }
            float x = sc_s[0][bbx * 8 + i][hh] + sc_s[1][bbx * 8 + j][hh];
            x = x > 0.f ? x : 0.2f * x;
            e[i] = x; m = fmaxf(m, x);
        }
        float s = 0.f;
        #pragma unroll
        for (int i = 0; i < NA; i++) {
            float ex = (i == j) ? 0.f : expf(e[i] - m);
            e[i] = ex; s += ex;
        }
        float inv = 1.f / (s + 1e-16f);
        #pragma unroll
        for (int i = 0; i < NA; i++) al[bbx][i][j][hh] = e[i] * inv;
    }
    __syncthreads();

    for (int idx = t; idx < 512; idx += 256)
        g_alpha[(size_t)blockIdx.x * 512 + idx] = ((const float*)al)[idx];
    if (t < 128) {
        int bbx = t >> 6, i = (t >> 3) & 7, j = t & 7;
        const float* a4 = &al[bbx][i][j][0];
        aw[bbx][i][j] = a4[0] + a4[1] + a4[2] + a4[3];
    }
    __syncthreads();

    for (int idx = t; idx < 16 * GD; idx += 256) {
        int aa = idx >> 6, g = idx & 63;
        int bbx = aa >> 3, j = aa & 7;
        float acc = 0.f;
        #pragma unroll
        for (int i = 0; i < NA; i++)
            acc += h_s[bbx * 8 + i][g] * aw[bbx][i][j];
        g_keys_pre[(size_t)(n0 + aa) * KD + 1 + g] = fmaxf(0.25f * acc, 0.f);
        if (g == 0)
            g_keys_pre[(size_t)(n0 + aa) * KD] = aq[n0 + aa];
    }
}

// ---------------------------------------------------------------------------
// Kernel B: hypernet GEMM cols 0..63, 8x8 tile, f32x2 FMAs, double-buffered
// cp.async, interleaved streaming zero-fill. 128 regs/thread budget.
// ---------------------------------------------------------------------------
__device__ __forceinline__ void stageA(float* As, int o0, int n0, int t) {
    #pragma unroll
    for (int rep = 0; rep < 10; rep++) {          // TKC*64/256 float4 ops
        int idx = rep * TBB + t;
        int o = idx >> 6, q = idx & 63;
        unsigned sa = (unsigned)__cvta_generic_to_shared(As + o * TMB + q * 4);
        const float* src = g_obsT + (size_t)(o0 + o) * Ntot + n0 + q * 4;
        CPA16(sa, src);
    }
}
__device__ __forceinline__ void stageB(const float* __restrict__ Wh, float* Bs,
                                       int o0, int k, int t) {
    #pragma unroll
    for (int rep = 0; rep < 10; rep++) {          // TKC*64/256 4B ops
        int idx = rep * TBB + t;
        int o = idx >> 6, j = idx & 63;
        unsigned sa = (unsigned)__cvta_generic_to_shared(Bs + o * NCB + j);
        const float* src = Wh + (size_t)(o0 + o) * KDSQ + k * KD + j;
        CPA4(sa, src);
    }
}

__global__ __launch_bounds__(TBB, 2) void kB(const float* __restrict__ Wh,
                                             const float* __restrict__ bh,
                                             float* __restrict__ dout) {
    extern __shared__ float sm[];
    float* As = sm;                       // [2][40][256]
    float* Bs = sm + 2 * TKC * TMB;       // [2][40][64]
    float* keys_s = Bs + 2 * TKC * NCB;   // [256]

    int bx = blockIdx.x;
    int k  = bx >> 4;
    int n0 = (bx & 15) * TMB;
    int t = threadIdx.x;
    int rg = t >> 3, cg = t & 7;

    float4* zp = (float4*)(dout + OUT_DENSE);
    unsigned long long zi = (unsigned long long)bx * TBB + t;
    const unsigned long long zstride = (unsigned long long)GRIDB * TBB;
    const float4 zero4 = make_float4(0.f, 0.f, 0.f, 0.f);

    stageA(As, 0, n0, t);
    stageB(Wh, Bs, 0, k, t);
    asm volatile("cp.async.commit_group;");

    keys_s[t] = g_keys_pre[(size_t)(n0 + t) * KD + k];

    ull c[4][8];
    #pragma unroll
    for (int p = 0; p < 4; p++)
        #pragma unroll
        for (int j = 0; j < 8; j++) c[p][j] = 0ULL;

    for (int ch = 0; ch < 4; ch++) {
        if (ch < 3) {
            int nb = (ch + 1) & 1;
            stageA(As + nb * TKC * TMB, (ch + 1) * TKC, n0, t);
            stageB(Wh, Bs + nb * TKC * NCB, (ch + 1) * TKC, k, t);
            asm volatile("cp.async.commit_group;");
            asm volatile("cp.async.wait_group 1;");
        } else {
            asm volatile("cp.async.wait_group 0;");
        }
        __syncthreads();

        const float* Ap = As + (ch & 1) * TKC * TMB + rg * 8;
        const float* Bp = Bs + (ch & 1) * TKC * NCB + cg * 8;
        #pragma unroll 2
        for (int o = 0; o < TKC; o++) {
            ulonglong2 A0 = *(const ulonglong2*)Ap;
            ulonglong2 A1 = *(const ulonglong2*)(Ap + 4);
            float4 b0 = *(const float4*)Bp;
            float4 b1 = *(const float4*)(Bp + 4);
            ull w;
            PACK2(w, b0.x);
            FMA2(c[0][0], A0.x, w); FMA2(c[1][0], A0.y, w);
            FMA2(c[2][0], A1.x, w); FMA2(c[3][0], A1.y, w);
            PACK2(w, b0.y);
            FMA2(c[0][1], A0.x, w); FMA2(c[1][1], A0.y, w);
            FMA2(c[2][1], A1.x, w); FMA2(c[3][1], A1.y, w);
            PACK2(w, b0.z);
            FMA2(c[0][2], A0.x, w); FMA2(c[1][2], A0.y, w);
            FMA2(c[2][2], A1.x, w); FMA2(c[3][2], A1.y, w);
            PACK2(w, b0.w);
            FMA2(c[0][3], A0.x, w); FMA2(c[1][3], A0.y, w);
            FMA2(c[2][3], A1.x, w); FMA2(c[3][3], A1.y, w);
            PACK2(w, b1.x);
            FMA2(c[0][4], A0.x, w); FMA2(c[1][4], A0.y, w);
            FMA2(c[2][4], A1.x, w); FMA2(c[3][4], A1.y, w);
            PACK2(w, b1.y);
            FMA2(c[0][5], A0.x, w); FMA2(c[1][5], A0.y, w);
            FMA2(c[2][5], A1.x, w); FMA2(c[3][5], A1.y, w);
            PACK2(w, b1.z);
            FMA2(c[0][6], A0.x, w); FMA2(c[1][6], A0.y, w);
            FMA2(c[2][6], A1.x, w); FMA2(c[3][6], A1.y, w);
            PACK2(w, b1.w);
            FMA2(c[0][7], A0.x, w); FMA2(c[1][7], A0.y, w);
            FMA2(c[2][7], A1.x, w); FMA2(c[3][7], A1.y, w);
            Ap += TMB; Bp += NCB;
        }

        // hidden zero-fill (streaming, evict-first): 16 x 4 chunks = 64/thread
        #pragma unroll
        for (int z = 0; z < 16; z++) {
            if (zi < DENSE_F4) __stcs(&zp[zi], zero4);
            zi += zstride;
        }
        __syncthreads();
    }

    // epilogue: weighted-abs -> g_part[k][n][cg*8..+7]
    float bias[8];
    #pragma unroll
    for (int jj = 0; jj < 8; jj++) bias[jj] = bh[k * KD + cg * 8 + jj];

    float* gp = g_part + (size_t)k * Ntot * PP + (size_t)n0 * PP + cg * 8;
    #pragma unroll
    for (int p = 0; p < 4; p++) {
        int r0 = rg * 8 + 2 * p;
        float k0 = keys_s[r0], k1 = keys_s[r0 + 1];
        float v0[8], v1[8];
        #pragma unroll
        for (int jj = 0; jj < 8; jj++) {
            float2 cv = *(float2*)&c[p][jj];
            v0[jj] = k0 * fabsf(cv.x + bias[jj]);
            v1[jj] = k1 * fabsf(cv.y + bias[jj]);
        }
        float* p0 = gp + (size_t)r0 * PP;
        float* p1 = p0 + PP;
        *(float4*)p0 = make_float4(v0[0], v0[1], v0[2], v0[3]);
        *(float4*)(p0 + 4) = make_float4(v0[4], v0[5], v0[6], v0[7]);
        *(float4*)p1 = make_float4(v1[0], v1[1], v1[2], v1[3]);
        *(float4*)(p1 + 4) = make_float4(v1[4], v1[5], v1[6], v1[7]);
    }
}

// ---------------------------------------------------------------------------
// Kernel J: j=64 column for all (n,k). Grid = 16 ntiles x 13 kgroups(5 k).
// ---------------------------------------------------------------------------
__global__ __launch_bounds__(160) void kJ(const float* __restrict__ Wh,
                                          const float* __restrict__ bh) {
    __shared__ float W64[5][OB];      // [kk][o]
    __shared__ float keys_s[5][TMB];  // [kk][r]  (keys_pre at k)

    int bx = blockIdx.x;
    int nt = bx & 15, kg = bx >> 4;
    int n0 = nt * TMB;
    int t = threadIdx.x;

    for (int idx = t; idx < 5 * OB; idx += 160) {
        int kk = idx / OB, o = idx - kk * OB;
        W64[kk][o] = Wh[(size_t)o * KDSQ + (kg * 5 + kk) * KD + 64];
    }
    for (int idx = t; idx < 5 * TMB; idx += 160) {
        int kk = idx >> 8, r = idx & 255;
        keys_s[kk][r] = g_keys_pre[(size_t)(n0 + r) * KD + kg * 5 + kk];
    }
    __syncthreads();

    int rg = t / 5, kk = t - (t / 5) * 5;   // 32 rowgroups x 5 k
    int k = kg * 5 + kk;
    float c[8];
    #pragma unroll
    for (int i = 0; i < 8; i++) c[i] = 0.f;

    #pragma unroll 4
    for (int o = 0; o < OB; o++) {
        float w = W64[kk][o];
        const float4* ap = (const float4*)(g_obsT + (size_t)o * Ntot + n0 + rg * 8);
        float4 a0 = ap[0], a1 = ap[1];
        c[0] += a0.x * w; c[1] += a0.y * w; c[2] += a0.z * w; c[3] += a0.w * w;
        c[4] += a1.x * w; c[5] += a1.y * w; c[6] += a1.z * w; c[7] += a1.w * w;
    }

    float bias = bh[k * KD + 64];
    float* gp = g_part + (size_t)k * Ntot * PP + (size_t)(n0 + rg * 8) * PP + 64;
    #pragma unroll
    for (int i = 0; i < 8; i++)
        gp[(size_t)i * PP] = keys_s[kk][rg * 8 + i] * fabsf(c[i] + bias);
}

// ---------------------------------------------------------------------------
// Kernel C: reduce 65 k-partials + elu, attention mixer, head weights, V.
// ---------------------------------------------------------------------------
__global__ __launch_bounds__(128) void kC(const float* __restrict__ aq,
                                          const float* __restrict__ states,
                                          const float* __restrict__ Wq,
                                          const float* __restrict__ Wk,
                                          const float* __restrict__ Wv1,
                                          const float* __restrict__ bv1,
                                          const float* __restrict__ Wv2,
                                          const float* __restrict__ bv2,
                                          const float* __restrict__ Ww1,
                                          const float* __restrict__ bw1,
                                          const float* __restrict__ Ww2,
                                          const float* __restrict__ bw2,
                                          float* __restrict__ dout) {
    int b = blockIdx.x, t = threadIdx.x;
    __shared__ float st_s[SD];
    __shared__ float keys_s[NA][KD];
    __shared__ float kvec[NA][NU];
    __shared__ float q_s[NU];
    __shared__ float hid[64], hv[32];
    __shared__ float hw_s[NH], v_s;
    __shared__ float outh[NH];

    for (int i = t; i < SD; i += 128) st_s[i] = states[(size_t)b * SD + i];

    const size_t KSTR = (size_t)Ntot * PP;
    for (int idx = t; idx < NA * KD; idx += 128) {
        int a = idx / KD, j = idx - (idx / KD) * KD;
        const float* p = g_part + (size_t)(b * NA + a) * PP + j;
        float s = 0.f;
        #pragma unroll 13
        for (int kg = 0; kg < KD; kg++) s += p[(size_t)kg * KSTR];
        keys_s[a][j] = (s > 0.f) ? s : expm1f(s);
    }
    __syncthreads();

    for (int idx = t; idx < NA * NU; idx += 128) {
        int a = idx / NU, u = idx & 31;
        float s = 0.f;
        #pragma unroll 5
        for (int j = 0; j < KD; j++) s += keys_s[a][j] * Wk[j * NU + u];
        kvec[a][u] = s;
    }
    if (t < NU) {
        float s = 0.f;
        for (int o = 0; o < SD; o++) s += st_s[o] * Wq[o * NU + t];
        q_s[t] = s;
    } else if (t < 96) {
        int x = t - 32;
        float s = bw1[x];
        for (int o = 0; o < SD; o++) s += st_s[o] * Ww1[o * 64 + x];
        hid[x] = fmaxf(s, 0.f);
    } else {
        int x = t - 96;
        float s = bv1[x];
        for (int o = 0; o < SD; o++) s += st_s[o] * Wv1[o * NU + x];
        hv[x] = fmaxf(s, 0.f);
    }
    __syncthreads();

    if (t < NH) {
        float s = bw2[t];
        #pragma unroll
        for (int x = 0; x < 64; x++) s += hid[x] * Ww2[x * NH + t];
        hw_s[t] = s * s;
    } else if (t == NH) {
        float s = bv2[0];
        #pragma unroll
        for (int x = 0; x < 32; x++) s += hv[x] * Wv2[x];
        v_s = s;
    }
    __syncthreads();

    if (t < NH) {
        int hh = t;
        float sc[NA]; float m = -1e30f;
        #pragma unroll
        for (int a = 0; a < NA; a++) {
            float s = 0.f;
            #pragma unroll
            for (int dd = 0; dd < 8; dd++)
                s += q_s[hh * 8 + dd] * kvec[a][hh * 8 + dd];
            s *= 0.35355339059327373f;
            sc[a] = s; m = fmaxf(m, s);
        }
        float sum = 0.f;
        #pragma unroll
        for (int a = 0; a < NA; a++) { sc[a] = expf(sc[a] - m); sum += sc[a]; }
        float inv = 1.f / sum;
        float oh = 0.f;
        #pragma unroll
        for (int a = 0; a < NA; a++) {
            float at = sc[a] * inv;
            dout[OUT_ATTN + b * 32 + hh * 8 + a] = at;
            oh += at * aq[b * NA + a];
        }
        outh[hh] = oh * hw_s[hh];
    }
    __syncthreads();
    if (t == 0) dout[b] = outh[0] + outh[1] + outh[2] + outh[3] + v_s;

    for (int idx = t; idx < 256; idx += 128) {
        int i = idx >> 5, j = (idx >> 2) & 7, hh = idx & 3;
        dout[OUT_DENSE +
             (((size_t)(b * NA + i)) * Ntot + b * NA + j) * NH + hh] =
            g_alpha[b * 256 + idx];
    }
}

// ---------------------------------------------------------------------------
extern "C" void kernel_launch(void* const* d_in, const int* in_sizes, int n_in,
                              void* d_out, int out_size) {
    const float* aq     = (const float*)d_in[0];
    const float* obs    = (const float*)d_in[1];
    const float* states = (const float*)d_in[2];
    // d_in[3] = edge_index (deterministic; unused)
    const float* Wg   = (const float*)d_in[4];
    const float* bg   = (const float*)d_in[5];
    const float* asrc = (const float*)d_in[6];
    const float* adst = (const float*)d_in[7];
    const float* Wh   = (const float*)d_in[8];
    const float* bh   = (const float*)d_in[9];
    const float* Wq   = (const float*)d_in[10];
    const float* Wk   = (const float*)d_in[11];
    const float* Wv1  = (const float*)d_in[12];
    const float* bv1  = (const float*)d_in[13];
    const float* Wv2  = (const float*)d_in[14];
    const float* bv2  = (const float*)d_in[15];
    const float* Ww1  = (const float*)d_in[16];
    const float* bw1  = (const float*)d_in[17];
    const float* Ww2  = (const float*)d_in[18];
    const float* bw2  = (const float*)d_in[19];
    float* out = (float*)d_out;

    const int kb_smem = (2 * TKC * TMB + 2 * TKC * NCB + TMB) * 4;   // ~101 KB
    cudaFuncSetAttribute(kB, cudaFuncAttributeMaxDynamicSharedMemorySize, kb_smem);

    kA<<<256, 256>>>(aq, obs, Wg, bg, asrc, adst);
    kB<<<GRIDB, TBB, kb_smem>>>(Wh, bh, out);
    kJ<<<16 * 13, 160>>>(Wh, bh);
    kC<<<Bsz, 128>>>(aq, states, Wq, Wk, Wv1, bv1, Wv2, bv2,
                     Ww1, bw1, Ww2, bw2, out);
}